// round 3
// baseline (speedup 1.0000x reference)
#include <cuda_runtime.h>
#include <cstdint>

// ---------------------------------------------------------------------------
// LinearAttention  (B=16, H=W=64, DIM=512, HEADS=8, DIM_HEAD=64)
//
//   qkv = x @ w_qkv                        [65536,512]x[512,1536]   (3xTF32 mma)
//   q,k,v -> head layout [b*8+h][c][n],  n = h_idx*64 + w_idx
//   k = softmax(k, axis=n)
//   ctx[d][e]  = sum_n k[d][n] * v[e][n]   per (b,h)
//   out[e][n]  = sum_d ctx[d][e] * q[d][n] per (b,h)
//   attn[b][n%64][n/64][h*64+e] = out      (einops spatial transpose)
//   final = attn @ w_out + b_out           [65536,512]x[512,512]    (3xTF32 mma)
// ---------------------------------------------------------------------------

#define NTOT (16 * 512 * 4096)

__device__ float g_q[NTOT];
__device__ float g_k[NTOT];
__device__ float g_v[NTOT];
__device__ float g_ctx[128 * 64 * 64];
__device__ float g_attn[NTOT];

// ---- tf32 helpers ---------------------------------------------------------
static __device__ __forceinline__ uint32_t f2tf(float x) {
    uint32_t r;
    asm("cvt.rna.tf32.f32 %0, %1;" : "=r"(r) : "f"(x));
    return r;
}
// split a into hi (tf32) + lo (tf32 of the residual)
static __device__ __forceinline__ void tf32_split(float a, uint32_t& hi, uint32_t& lo) {
    hi = f2tf(a);
    lo = f2tf(a - __uint_as_float(hi));
}
static __device__ __forceinline__ void mma8(float* c, const uint32_t* a, const uint32_t* b) {
    asm volatile(
        "mma.sync.aligned.m16n8k8.row.col.f32.tf32.tf32.f32 "
        "{%0,%1,%2,%3}, {%4,%5,%6,%7}, {%8,%9}, {%0,%1,%2,%3};\n"
        : "+f"(c[0]), "+f"(c[1]), "+f"(c[2]), "+f"(c[3])
        : "r"(a[0]), "r"(a[1]), "r"(a[2]), "r"(a[3]), "r"(b[0]), "r"(b[1]));
}

// ---------------------------------------------------------------------------
// 3xTF32 GEMM: 128x128 block tile, 256 threads = 8 warps (4 m x 2 n),
// each warp 32x64 = 2x8 m16n8k8 tiles, K-step 8.
// Two-stage pipeline: register prefetch of step k+1 issued before compute of
// step k; double-buffered shared tiles; one __syncthreads per step.
// MODE 0: C scatter-stored into g_q/g_k/g_v head-major layout (qkv GEMM)
// MODE 1: A = g_attn, C = d_out row-major + bias (output GEMM)
// ---------------------------------------------------------------------------
#define SPAD 136

template <int MODE>
__global__ __launch_bounds__(256)
void tgemm_kernel(const float* __restrict__ A,
                  const float* __restrict__ B,
                  float* __restrict__ C,
                  const float* __restrict__ bias,
                  int N, int K)
{
    __shared__ float As[2][8][SPAD];   // [buf][k][m], padded
    __shared__ float Bs[2][8][SPAD];   // [buf][k][n], padded

    const int tid = threadIdx.x;
    const int lane = tid & 31;
    const int wid = tid >> 5;
    const int wm = (wid & 3) * 32;     // warp m-origin within block
    const int wn = (wid >> 2) * 64;    // warp n-origin within block
    const int grp = lane >> 2;         // 0..7
    const int tg = lane & 3;           // 0..3
    const int bm = blockIdx.y * 128;
    const int bn = blockIdx.x * 128;

    const float* Abase = (MODE == 0) ? A : g_attn;

    float acc[2][8][4];
#pragma unroll
    for (int i = 0; i < 2; i++)
#pragma unroll
        for (int j = 0; j < 8; j++)
#pragma unroll
            for (int r = 0; r < 4; r++) acc[i][j][r] = 0.f;

    // global->shared staging addressing
    const int arow = tid >> 1;
    const int acol = (tid & 1) << 2;
    const int brow = tid >> 5;
    const int bcol = (tid & 31) << 2;
    const float* Ap = Abase + (size_t)(bm + arow) * K + acol;
    const float* Bp = B + (size_t)brow * N + bn + bcol;

    // prologue: stage k0 = 0 into buffer 0
    {
        float4 av = *(const float4*)(Ap);
        float4 bv = *(const float4*)(Bp);
        As[0][acol + 0][arow] = av.x;
        As[0][acol + 1][arow] = av.y;
        As[0][acol + 2][arow] = av.z;
        As[0][acol + 3][arow] = av.w;
        *(float4*)&Bs[0][brow][bcol] = bv;
    }
    __syncthreads();

    int buf = 0;
    for (int k0 = 0; k0 < K; k0 += 8) {
        // issue next tile's global loads before compute (latency overlap)
        const bool more = (k0 + 8) < K;
        float4 av, bv;
        if (more) {
            av = *(const float4*)(Ap + k0 + 8);
            bv = *(const float4*)(Bp + (size_t)(k0 + 8) * N);
        }

        // build fragments (m16n8k8 row.col layouts) from current buffer
        uint32_t ah[2][4], al[2][4], bh[8][2], bl[8][2];
#pragma unroll
        for (int i = 0; i < 2; i++) {
            const int mb = wm + i * 16 + grp;
            tf32_split(As[buf][tg][mb],         ah[i][0], al[i][0]);
            tf32_split(As[buf][tg][mb + 8],     ah[i][1], al[i][1]);
            tf32_split(As[buf][tg + 4][mb],     ah[i][2], al[i][2]);
            tf32_split(As[buf][tg + 4][mb + 8], ah[i][3], al[i][3]);
        }
#pragma unroll
        for (int j = 0; j < 8; j++) {
            const int nb = wn + j * 8 + grp;
            tf32_split(Bs[buf][tg][nb],     bh[j][0], bl[j][0]);
            tf32_split(Bs[buf][tg + 4][nb], bh[j][1], bl[j][1]);
        }

#pragma unroll
        for (int i = 0; i < 2; i++)
#pragma unroll
            for (int j = 0; j < 8; j++) {
                mma8(acc[i][j], ah[i], bh[j]);   // hi*hi
                mma8(acc[i][j], ah[i], bl[j]);   // hi*lo
                mma8(acc[i][j], al[i], bh[j]);   // lo*hi
            }

        // stage next tile into the other buffer (waits on LDG after compute)
        if (more) {
            const int nb_ = buf ^ 1;
            As[nb_][acol + 0][arow] = av.x;
            As[nb_][acol + 1][arow] = av.y;
            As[nb_][acol + 2][arow] = av.z;
            As[nb_][acol + 3][arow] = av.w;
            *(float4*)&Bs[nb_][brow][bcol] = bv;
        }
        __syncthreads();
        buf ^= 1;
    }

    // epilogues --------------------------------------------------------------
    if (MODE == 0) {
        // C row m = spatial (b*4096 + n), col j = part*512 + h*64 + c
#pragma unroll
        for (int i = 0; i < 2; i++) {
            const int m0 = bm + wm + i * 16 + grp;     // row of c0/c1
            const int m1 = m0 + 8;                     // row of c2/c3
            const int b0 = m0 >> 12, n0 = m0 & 4095;
            const int b1 = m1 >> 12, n1 = m1 & 4095;
#pragma unroll
            for (int j = 0; j < 8; j++) {
                const int jc = bn + wn + j * 8 + tg * 2;
#pragma unroll
                for (int jj = 0; jj < 2; jj++) {
                    const int jcol = jc + jj;
                    const int part = jcol >> 9;
                    const int rem = jcol & 511;
                    float* dst = (part == 0) ? g_q : (part == 1) ? g_k : g_v;
                    dst[(size_t)(b0 * 512 + rem) * 4096 + n0] = acc[i][j][jj];
                    dst[(size_t)(b1 * 512 + rem) * 4096 + n1] = acc[i][j][2 + jj];
                }
            }
        }
    } else {
#pragma unroll
        for (int i = 0; i < 2; i++) {
            const int m0 = bm + wm + i * 16 + grp;
#pragma unroll
            for (int j = 0; j < 8; j++) {
                const int jc = bn + wn + j * 8 + tg * 2;
                const float bx = bias[jc], by = bias[jc + 1];
                *(float2*)&C[(size_t)m0 * N + jc] =
                    make_float2(acc[i][j][0] + bx, acc[i][j][1] + by);
                *(float2*)&C[(size_t)(m0 + 8) * N + jc] =
                    make_float2(acc[i][j][2] + bx, acc[i][j][3] + by);
            }
        }
    }
}

// ---------------------------------------------------------------------------
// Softmax over the 4096-wide spatial axis, in place on g_k. (unchanged)
// ---------------------------------------------------------------------------
__global__ __launch_bounds__(256)
void softmax_rows_kernel()
{
    __shared__ float row[4096];
    __shared__ float red[256];
    const int r = blockIdx.x;
    const int tid = threadIdx.x;
    float* p = g_k + (size_t)r * 4096;

    float m = -1e30f;
    for (int i = tid; i < 4096; i += 256) {
        float v = p[i];
        row[i] = v;
        m = fmaxf(m, v);
    }
    red[tid] = m;
    __syncthreads();
    for (int s = 128; s > 0; s >>= 1) {
        if (tid < s) red[tid] = fmaxf(red[tid], red[tid + s]);
        __syncthreads();
    }
    const float mx = red[0];
    __syncthreads();

    float sum = 0.f;
    for (int i = tid; i < 4096; i += 256) {
        float e = __expf(row[i] - mx);
        row[i] = e;
        sum += e;
    }
    red[tid] = sum;
    __syncthreads();
    for (int s = 128; s > 0; s >>= 1) {
        if (tid < s) red[tid] += red[tid + s];
        __syncthreads();
    }
    const float inv = 1.f / red[0];
    for (int i = tid; i < 4096; i += 256)
        p[i] = row[i] * inv;
}

// ---------------------------------------------------------------------------
// ctx[bh][d][e] = sum_n k[bh][d][n] * v[bh][e][n]   (unchanged)
// ---------------------------------------------------------------------------
__global__ __launch_bounds__(256)
void context_kernel()
{
    const int bh = blockIdx.x;
    __shared__ float ks[64][64];   // [n][d]
    __shared__ float vs[64][64];   // [n][e]
    const int tid = threadIdx.x;
    const int tx = tid & 15;
    const int ty = tid >> 4;
    const float* kb = g_k + (size_t)bh * 64 * 4096;
    const float* vb = g_v + (size_t)bh * 64 * 4096;

    float acc[4][4];
#pragma unroll
    for (int i = 0; i < 4; i++)
#pragma unroll
        for (int j = 0; j < 4; j++) acc[i][j] = 0.f;

    const int lr = tid >> 4;
    const int lc = (tid & 15) << 2;

    for (int n0 = 0; n0 < 4096; n0 += 64) {
#pragma unroll
        for (int rr = 0; rr < 4; rr++) {
            int d = lr + rr * 16;
            float4 k4 = *(const float4*)&kb[(size_t)d * 4096 + n0 + lc];
            ks[lc + 0][d] = k4.x; ks[lc + 1][d] = k4.y;
            ks[lc + 2][d] = k4.z; ks[lc + 3][d] = k4.w;
            float4 v4 = *(const float4*)&vb[(size_t)d * 4096 + n0 + lc];
            vs[lc + 0][d] = v4.x; vs[lc + 1][d] = v4.y;
            vs[lc + 2][d] = v4.z; vs[lc + 3][d] = v4.w;
        }
        __syncthreads();
#pragma unroll 8
        for (int n = 0; n < 64; n++) {
            float4 a = *(float4*)&ks[n][tx * 4];
            float4 b = *(float4*)&vs[n][ty * 4];
            float ar[4] = {a.x, a.y, a.z, a.w};
            float br[4] = {b.x, b.y, b.z, b.w};
#pragma unroll
            for (int i = 0; i < 4; i++)
#pragma unroll
                for (int j = 0; j < 4; j++)
                    acc[i][j] += ar[i] * br[j];
        }
        __syncthreads();
    }

    float* cb = g_ctx + (size_t)bh * 4096;
#pragma unroll
    for (int i = 0; i < 4; i++)
        *(float4*)&cb[(size_t)(tx * 4 + i) * 64 + ty * 4] =
            make_float4(acc[i][0], acc[i][1], acc[i][2], acc[i][3]);
}

// ---------------------------------------------------------------------------
// attn: out[e][n] = sum_d ctx[d][e] * q[d][n]  (unchanged)
// ---------------------------------------------------------------------------
__global__ __launch_bounds__(256)
void apply_kernel()
{
    const int bh = blockIdx.x;
    const int nc = blockIdx.y;
    const int tid = threadIdx.x;
    __shared__ float cs[64][64];   // [d][e]

    const float* cb = g_ctx + (size_t)bh * 4096;
    float* csf = &cs[0][0];
#pragma unroll
    for (int r = 0; r < 4; r++) {
        int off = (tid + r * 256) * 4;
        *(float4*)&csf[off] = *(const float4*)&cb[off];
    }
    __syncthreads();

    const int n = nc * 256 + tid;
    const float* qb = g_q + (size_t)bh * 64 * 4096 + n;

    float acc[64];
#pragma unroll
    for (int e = 0; e < 64; e++) acc[e] = 0.f;

    for (int d = 0; d < 64; d++) {
        float qv = qb[(size_t)d * 4096];
#pragma unroll
        for (int e4 = 0; e4 < 64; e4 += 4) {
            float4 c4 = *(float4*)&cs[d][e4];
            acc[e4 + 0] += c4.x * qv;
            acc[e4 + 1] += c4.y * qv;
            acc[e4 + 2] += c4.z * qv;
            acc[e4 + 3] += c4.w * qv;
        }
    }

    const int b = bh >> 3, h = bh & 7;
    const int x = n >> 6, y = n & 63;
    float* ob = g_attn + ((size_t)((b * 64 + y) * 64 + x) * 512 + h * 64);
#pragma unroll
    for (int e4 = 0; e4 < 64; e4 += 4)
        *(float4*)&ob[e4] = make_float4(acc[e4 + 0], acc[e4 + 1],
                                        acc[e4 + 2], acc[e4 + 3]);
}

// ---------------------------------------------------------------------------
extern "C" void kernel_launch(void* const* d_in, const int* in_sizes, int n_in,
                              void* d_out, int out_size)
{
    const float* x     = (const float*)d_in[0];   // [16,64,64,512]
    const float* w_qkv = (const float*)d_in[1];   // [512,1536]
    const float* w_out = (const float*)d_in[2];   // [512,512]
    const float* b_out = (const float*)d_in[3];   // [512]
    float* out = (float*)d_out;                   // [16,64,64,512]

    // 1) qkv GEMM (3xTF32, pipelined) -> q/k/v head-major scratch
    tgemm_kernel<0><<<dim3(12, 512), 256>>>(x, w_qkv, nullptr, nullptr, 1536, 512);

    // 2) softmax over spatial axis, in place on k
    softmax_rows_kernel<<<8192, 256>>>();

    // 3) per-(b,h) context GEMM [64,4096]x[4096,64]
    context_kernel<<<128, 256>>>();

    // 4) per-(b,h) apply GEMM + spatial-transpose scatter into attn layout
    apply_kernel<<<dim3(128, 16), 256>>>();

    // 5) final GEMM (3xTF32, pipelined) + bias -> d_out
    tgemm_kernel<1><<<dim3(4, 512), 256>>>(nullptr, w_out, out, b_out, 512, 512);
}

// round 8
// speedup vs baseline: 1.7241x; 1.7241x over previous
#include <cuda_runtime.h>
#include <cstdint>

// ---------------------------------------------------------------------------
// LinearAttention  (B=16, H=W=64, DIM=512, HEADS=8, DIM_HEAD=64)
//
//   qkv = x @ w_qkv                        [65536,512]x[512,1536]  (3xBF16 mma)
//   q,k,v -> head layout [b*8+h][c][n],  n = h_idx*64 + w_idx
//   k = softmax(k, axis=n)
//   ctx[d][e]  = sum_n k[d][n] * v[e][n]   per (b,h)   (n split 4 ways)
//   out[e][n]  = sum_d ctx[d][e] * q[d][n] per (b,h)
//   attn[b][n%64][n/64][h*64+e] = out      (einops spatial transpose)
//   final = attn @ w_out + b_out           [65536,512]x[512,512]   (3xBF16 mma)
// ---------------------------------------------------------------------------

#define NTOT (16 * 512 * 4096)

__device__ float g_q[NTOT];
__device__ float g_k[NTOT];
__device__ float g_v[NTOT];
__device__ float g_ctxp[4][128 * 64 * 64];
__device__ float g_attn[NTOT];

// ---- bf16 split helpers ---------------------------------------------------
// split two floats (even k, odd k) into packed bf16x2 hi and bf16x2 lo.
// bf16x2 register layout: low 16 bits = even (smaller k), high = odd.
static __device__ __forceinline__ void split2(float e, float o,
                                              uint32_t& hi, uint32_t& lo) {
    uint32_t h;
    asm("cvt.rn.bf16x2.f32 %0, %1, %2;" : "=r"(h) : "f"(o), "f"(e));
    float he = __uint_as_float(h << 16);
    float ho = __uint_as_float(h & 0xffff0000u);
    float le = e - he;
    float lo_ = o - ho;
    asm("cvt.rn.bf16x2.f32 %0, %1, %2;" : "=r"(lo) : "f"(lo_), "f"(le));
    hi = h;
}

static __device__ __forceinline__ void mma16(float* c, const uint32_t* a,
                                             const uint32_t* b) {
    asm volatile(
        "mma.sync.aligned.m16n8k16.row.col.f32.bf16.bf16.f32 "
        "{%0,%1,%2,%3}, {%4,%5,%6,%7}, {%8,%9}, {%0,%1,%2,%3};\n"
        : "+f"(c[0]), "+f"(c[1]), "+f"(c[2]), "+f"(c[3])
        : "r"(a[0]), "r"(a[1]), "r"(a[2]), "r"(a[3]), "r"(b[0]), "r"(b[1]));
}

// ---------------------------------------------------------------------------
// 3xBF16 GEMM: 128x128 block tile, 256 threads = 8 warps (4 m x 2 n),
// each warp 32x64 = 2x8 m16n8k16 tiles, K-step 16.
// hi/lo split precomputed at staging into shared (bf16x2 pairs, fragment-ready).
// Two-stage pipeline: register prefetch of step k+1 before compute of step k,
// double-buffered shared, one __syncthreads per step.
// MODE 0: C scatter-stored into g_q/g_k/g_v head-major layout (qkv GEMM)
// MODE 1: A = g_attn, C = d_out row-major + bias (output GEMM)
// ---------------------------------------------------------------------------
#define SPAD2 136

template <int MODE>
__global__ __launch_bounds__(256)
void tgemm_kernel(const float* __restrict__ A,
                  const float* __restrict__ B,
                  float* __restrict__ C,
                  const float* __restrict__ bias,
                  int N, int K)
{
    // [buf][kpair 0..7][column], packed bf16x2 (k even in low half)
    __shared__ uint32_t Ah2[2][8][SPAD2], Al2[2][8][SPAD2];
    __shared__ uint32_t Bh2[2][8][SPAD2], Bl2[2][8][SPAD2];

    const int tid = threadIdx.x;
    const int lane = tid & 31;
    const int wid = tid >> 5;
    const int wm = (wid & 3) * 32;     // warp m-origin
    const int wn = (wid >> 2) * 64;    // warp n-origin
    const int grp = lane >> 2;         // 0..7
    const int tg = lane & 3;           // 0..3
    const int bm = blockIdx.y * 128;
    const int bn = blockIdx.x * 128;

    const float* Abase = (MODE == 0) ? A : g_attn;

    float acc[2][8][4];
#pragma unroll
    for (int i = 0; i < 2; i++)
#pragma unroll
        for (int j = 0; j < 8; j++)
#pragma unroll
            for (int r = 0; r < 4; r++) acc[i][j][r] = 0.f;

    // staging addressing:
    // A tile 128m x 16k: thread covers rows arow, arow+64 at float4 k-chunk akq
    const int arow = tid >> 2;          // 0..63
    const int akq  = tid & 3;           // k float4 index (k = akq*4..akq*4+3)
    // B tile 16k x 128n: thread owns k-pair bkp, 4 n columns at bn4
    const int bkp  = tid >> 5;          // 0..7
    const int bn4  = (tid & 31) * 4;

    const float* ApA = Abase + (size_t)(bm + arow) * K + akq * 4;
    const float* ApB = Abase + (size_t)(bm + arow + 64) * K + akq * 4;
    const float* BpA = B + (size_t)(2 * bkp) * N + bn + bn4;
    const float* BpB = B + (size_t)(2 * bkp + 1) * N + bn + bn4;

    // ---- stage one 16-k tile (from regs) into buffer b -------------------
    auto stage_store = [&](int b, const float4& av0, const float4& av1,
                           const float4& bv0, const float4& bv1) {
        uint32_t h, l;
        // A row arow
        split2(av0.x, av0.y, h, l);
        Ah2[b][2 * akq][arow] = h;      Al2[b][2 * akq][arow] = l;
        split2(av0.z, av0.w, h, l);
        Ah2[b][2 * akq + 1][arow] = h;  Al2[b][2 * akq + 1][arow] = l;
        // A row arow+64
        split2(av1.x, av1.y, h, l);
        Ah2[b][2 * akq][arow + 64] = h;     Al2[b][2 * akq][arow + 64] = l;
        split2(av1.z, av1.w, h, l);
        Ah2[b][2 * akq + 1][arow + 64] = h; Al2[b][2 * akq + 1][arow + 64] = l;
        // B: pair (even k from bv0, odd k from bv1) per n
        uint32_t bh_[4], bl_[4];
        split2(bv0.x, bv1.x, bh_[0], bl_[0]);
        split2(bv0.y, bv1.y, bh_[1], bl_[1]);
        split2(bv0.z, bv1.z, bh_[2], bl_[2]);
        split2(bv0.w, bv1.w, bh_[3], bl_[3]);
        *(uint4*)&Bh2[b][bkp][bn4] = make_uint4(bh_[0], bh_[1], bh_[2], bh_[3]);
        *(uint4*)&Bl2[b][bkp][bn4] = make_uint4(bl_[0], bl_[1], bl_[2], bl_[3]);
    };

    // prologue: stage k0 = 0 into buffer 0
    {
        float4 av0 = *(const float4*)(ApA);
        float4 av1 = *(const float4*)(ApB);
        float4 bv0 = *(const float4*)(BpA);
        float4 bv1 = *(const float4*)(BpB);
        stage_store(0, av0, av1, bv0, bv1);
    }
    __syncthreads();

    int buf = 0;
    for (int k0 = 0; k0 < K; k0 += 16) {
        const bool more = (k0 + 16) < K;
        float4 av0, av1, bv0, bv1;
        if (more) {
            av0 = *(const float4*)(ApA + k0 + 16);
            av1 = *(const float4*)(ApB + k0 + 16);
            bv0 = *(const float4*)(BpA + (size_t)(k0 + 16) * N);
            bv1 = *(const float4*)(BpB + (size_t)(k0 + 16) * N);
        }

        // fragment loads (m16n8k16 row.col; verified against PTX ISA layout,
        // same index structure as the passing tf32 kernel with k in bf16x2 pairs)
        uint32_t ah[2][4], al[2][4], bh[8][2], bl[8][2];
#pragma unroll
        for (int i = 0; i < 2; i++) {
            const int mb = wm + i * 16 + grp;
            ah[i][0] = Ah2[buf][tg][mb];
            ah[i][1] = Ah2[buf][tg][mb + 8];
            ah[i][2] = Ah2[buf][tg + 4][mb];
            ah[i][3] = Ah2[buf][tg + 4][mb + 8];
            al[i][0] = Al2[buf][tg][mb];
            al[i][1] = Al2[buf][tg][mb + 8];
            al[i][2] = Al2[buf][tg + 4][mb];
            al[i][3] = Al2[buf][tg + 4][mb + 8];
        }
#pragma unroll
        for (int j = 0; j < 8; j++) {
            const int nb = wn + j * 8 + grp;
            bh[j][0] = Bh2[buf][tg][nb];
            bh[j][1] = Bh2[buf][tg + 4][nb];
            bl[j][0] = Bl2[buf][tg][nb];
            bl[j][1] = Bl2[buf][tg + 4][nb];
        }

#pragma unroll
        for (int i = 0; i < 2; i++)
#pragma unroll
            for (int j = 0; j < 8; j++) {
                mma16(acc[i][j], ah[i], bh[j]);   // hi*hi
                mma16(acc[i][j], ah[i], bl[j]);   // hi*lo
                mma16(acc[i][j], al[i], bh[j]);   // lo*hi
            }

        if (more) stage_store(buf ^ 1, av0, av1, bv0, bv1);
        __syncthreads();
        buf ^= 1;
    }

    // epilogues (unchanged from the passing kernel) --------------------------
    if (MODE == 0) {
#pragma unroll
        for (int i = 0; i < 2; i++) {
            const int m0 = bm + wm + i * 16 + grp;
            const int m1 = m0 + 8;
            const int b0 = m0 >> 12, n0 = m0 & 4095;
            const int b1 = m1 >> 12, n1 = m1 & 4095;
#pragma unroll
            for (int j = 0; j < 8; j++) {
                const int jc = bn + wn + j * 8 + tg * 2;
#pragma unroll
                for (int jj = 0; jj < 2; jj++) {
                    const int jcol = jc + jj;
                    const int part = jcol >> 9;
                    const int rem = jcol & 511;
                    float* dst = (part == 0) ? g_q : (part == 1) ? g_k : g_v;
                    dst[(size_t)(b0 * 512 + rem) * 4096 + n0] = acc[i][j][jj];
                    dst[(size_t)(b1 * 512 + rem) * 4096 + n1] = acc[i][j][2 + jj];
                }
            }
        }
    } else {
#pragma unroll
        for (int i = 0; i < 2; i++) {
            const int m0 = bm + wm + i * 16 + grp;
#pragma unroll
            for (int j = 0; j < 8; j++) {
                const int jc = bn + wn + j * 8 + tg * 2;
                const float bx = bias[jc], by = bias[jc + 1];
                *(float2*)&C[(size_t)m0 * N + jc] =
                    make_float2(acc[i][j][0] + bx, acc[i][j][1] + by);
                *(float2*)&C[(size_t)(m0 + 8) * N + jc] =
                    make_float2(acc[i][j][2] + bx, acc[i][j][3] + by);
            }
        }
    }
}

// ---------------------------------------------------------------------------
// Softmax over the 4096-wide spatial axis, in place on g_k. (unchanged)
// ---------------------------------------------------------------------------
__global__ __launch_bounds__(256)
void softmax_rows_kernel()
{
    __shared__ float row[4096];
    __shared__ float red[256];
    const int r = blockIdx.x;
    const int tid = threadIdx.x;
    float* p = g_k + (size_t)r * 4096;

    float m = -1e30f;
    for (int i = tid; i < 4096; i += 256) {
        float v = p[i];
        row[i] = v;
        m = fmaxf(m, v);
    }
    red[tid] = m;
    __syncthreads();
    for (int s = 128; s > 0; s >>= 1) {
        if (tid < s) red[tid] = fmaxf(red[tid], red[tid + s]);
        __syncthreads();
    }
    const float mx = red[0];
    __syncthreads();

    float sum = 0.f;
    for (int i = tid; i < 4096; i += 256) {
        float e = __expf(row[i] - mx);
        row[i] = e;
        sum += e;
    }
    red[tid] = sum;
    __syncthreads();
    for (int s = 128; s > 0; s >>= 1) {
        if (tid < s) red[tid] += red[tid + s];
        __syncthreads();
    }
    const float inv = 1.f / red[0];
    for (int i = tid; i < 4096; i += 256)
        p[i] = row[i] * inv;
}

// ---------------------------------------------------------------------------
// ctx partial: g_ctxp[part][bh][d][e] = sum over n in part's 1024-chunk of
// k[bh][d][n] * v[bh][e][n].  grid (128 bh, 4 parts).
// ---------------------------------------------------------------------------
__global__ __launch_bounds__(256)
void context_kernel()
{
    const int bh = blockIdx.x;
    const int part = blockIdx.y;
    __shared__ float ks[64][64];   // [n][d]
    __shared__ float vs[64][64];   // [n][e]
    const int tid = threadIdx.x;
    const int tx = tid & 15;
    const int ty = tid >> 4;
    const float* kb = g_k + (size_t)bh * 64 * 4096;
    const float* vb = g_v + (size_t)bh * 64 * 4096;

    float acc[4][4];
#pragma unroll
    for (int i = 0; i < 4; i++)
#pragma unroll
        for (int j = 0; j < 4; j++) acc[i][j] = 0.f;

    const int lr = tid >> 4;
    const int lc = (tid & 15) << 2;
    const int nbeg = part * 1024;

    for (int n0 = nbeg; n0 < nbeg + 1024; n0 += 64) {
#pragma unroll
        for (int rr = 0; rr < 4; rr++) {
            int d = lr + rr * 16;
            float4 k4 = *(const float4*)&kb[(size_t)d * 4096 + n0 + lc];
            ks[lc + 0][d] = k4.x; ks[lc + 1][d] = k4.y;
            ks[lc + 2][d] = k4.z; ks[lc + 3][d] = k4.w;
            float4 v4 = *(const float4*)&vb[(size_t)d * 4096 + n0 + lc];
            vs[lc + 0][d] = v4.x; vs[lc + 1][d] = v4.y;
            vs[lc + 2][d] = v4.z; vs[lc + 3][d] = v4.w;
        }
        __syncthreads();
#pragma unroll 8
        for (int n = 0; n < 64; n++) {
            float4 a = *(float4*)&ks[n][tx * 4];
            float4 b = *(float4*)&vs[n][ty * 4];
            float ar[4] = {a.x, a.y, a.z, a.w};
            float br[4] = {b.x, b.y, b.z, b.w};
#pragma unroll
            for (int i = 0; i < 4; i++)
#pragma unroll
                for (int j = 0; j < 4; j++)
                    acc[i][j] += ar[i] * br[j];
        }
        __syncthreads();
    }

    float* cb = g_ctxp[part] + (size_t)bh * 4096;
#pragma unroll
    for (int i = 0; i < 4; i++)
        *(float4*)&cb[(size_t)(tx * 4 + i) * 64 + ty * 4] =
            make_float4(acc[i][0], acc[i][1], acc[i][2], acc[i][3]);
}

// ---------------------------------------------------------------------------
// attn: out[e][n] = sum_d ctx[d][e] * q[d][n], spatial-transposed store.
// grid (128 bh, 32 n-chunks of 128), 256 threads: tid>>7 picks e-half (32 e),
// tid&127 picks n. acc[32] -> ~60 regs -> good occupancy.
// Sums the 4 context partials while loading shared.
// ---------------------------------------------------------------------------
__global__ __launch_bounds__(256)
void apply_kernel()
{
    const int bh = blockIdx.x;
    const int nc = blockIdx.y;
    const int tid = threadIdx.x;
    __shared__ float cs[64][64];   // [d][e]

    const size_t coff = (size_t)bh * 4096;
    float* csf = &cs[0][0];
#pragma unroll
    for (int r = 0; r < 4; r++) {
        int off = (tid + r * 256) * 4;
        float4 s0 = *(const float4*)&g_ctxp[0][coff + off];
        float4 s1 = *(const float4*)&g_ctxp[1][coff + off];
        float4 s2 = *(const float4*)&g_ctxp[2][coff + off];
        float4 s3 = *(const float4*)&g_ctxp[3][coff + off];
        *(float4*)&csf[off] = make_float4(s0.x + s1.x + s2.x + s3.x,
                                          s0.y + s1.y + s2.y + s3.y,
                                          s0.z + s1.z + s2.z + s3.z,
                                          s0.w + s1.w + s2.w + s3.w);
    }
    __syncthreads();

    const int eh = tid >> 7;               // e-half 0/1
    const int e0 = eh * 32;
    const int n = nc * 128 + (tid & 127);
    const float* qb = g_q + (size_t)bh * 64 * 4096 + n;

    float acc[32];
#pragma unroll
    for (int e = 0; e < 32; e++) acc[e] = 0.f;

#pragma unroll 2
    for (int d0 = 0; d0 < 64; d0 += 4) {
        float q0 = qb[(size_t)(d0 + 0) * 4096];
        float q1 = qb[(size_t)(d0 + 1) * 4096];
        float q2 = qb[(size_t)(d0 + 2) * 4096];
        float q3 = qb[(size_t)(d0 + 3) * 4096];
#pragma unroll
        for (int e4 = 0; e4 < 32; e4 += 4) {
            float4 c0 = *(float4*)&cs[d0 + 0][e0 + e4];
            float4 c1 = *(float4*)&cs[d0 + 1][e0 + e4];
            float4 c2 = *(float4*)&cs[d0 + 2][e0 + e4];
            float4 c3 = *(float4*)&cs[d0 + 3][e0 + e4];
            acc[e4 + 0] += c0.x * q0 + c1.x * q1 + c2.x * q2 + c3.x * q3;
            acc[e4 + 1] += c0.y * q0 + c1.y * q1 + c2.y * q2 + c3.y * q3;
            acc[e4 + 2] += c0.z * q0 + c1.z * q1 + c2.z * q2 + c3.z * q3;
            acc[e4 + 3] += c0.w * q0 + c1.w * q1 + c2.w * q2 + c3.w * q3;
        }
    }

    const int b = bh >> 3, h = bh & 7;
    const int x = n >> 6, y = n & 63;
    float* ob = g_attn + ((size_t)((b * 64 + y) * 64 + x) * 512 + h * 64 + e0);
#pragma unroll
    for (int e4 = 0; e4 < 32; e4 += 4)
        *(float4*)&ob[e4] = make_float4(acc[e4 + 0], acc[e4 + 1],
                                        acc[e4 + 2], acc[e4 + 3]);
}

// ---------------------------------------------------------------------------
extern "C" void kernel_launch(void* const* d_in, const int* in_sizes, int n_in,
                              void* d_out, int out_size)
{
    const float* x     = (const float*)d_in[0];   // [16,64,64,512]
    const float* w_qkv = (const float*)d_in[1];   // [512,1536]
    const float* w_out = (const float*)d_in[2];   // [512,512]
    const float* b_out = (const float*)d_in[3];   // [512]
    float* out = (float*)d_out;                   // [16,64,64,512]

    // 1) qkv GEMM (3xBF16 mma) -> q/k/v head-major scratch
    tgemm_kernel<0><<<dim3(12, 512), 256>>>(x, w_qkv, nullptr, nullptr, 1536, 512);

    // 2) softmax over spatial axis, in place on k
    softmax_rows_kernel<<<8192, 256>>>();

    // 3) per-(b,h) context GEMM, n split into 4 partials
    context_kernel<<<dim3(128, 4), 256>>>();

    // 4) apply GEMM (sums partials) + spatial-transpose scatter
    apply_kernel<<<dim3(128, 32), 256>>>();

    // 5) final GEMM (3xBF16 mma) + bias -> d_out
    tgemm_kernel<1><<<dim3(4, 512), 256>>>(nullptr, w_out, out, b_out, 512, 512);
}